// round 2
// baseline (speedup 1.0000x reference)
#include <cuda_runtime.h>
#include <cstdint>

// Problem constants (fixed by the reference)
#define NN 50000
#define EE 800000
#define FIN 256
#define HH 64
#define NGR 64
#define NCL 4

// ---------------- scratch (device globals; no allocs allowed) ----------------
__device__ float g_deg[NN];          // float degree incl. self loop
__device__ int   g_edeg[NN];         // int in-edge count (no self loop)
__device__ float g_dinv[NN];
__device__ int   g_off[NN + 1];      // CSR offsets by dst
__device__ int   g_cursor[NN];       // scatter cursors
__device__ int   g_csrc[EE];         // CSR src lists
__device__ float g_h[(size_t)NN * HH];   // X@W result (both layers)
__device__ float g_a[(size_t)NN * HH];   // aggregated output (both layers)
__device__ float g_pool[NGR * HH];
__device__ float g_cnt[NGR];
__device__ float g_z[NGR * 128];

// ---------------- init ----------------
__global__ void k_init() {
    int t = blockIdx.x * blockDim.x + threadIdx.x;
    if (t < NN) { g_deg[t] = 1.0f; g_edeg[t] = 0; }
    if (t < NGR * HH) g_pool[t] = 0.0f;
    if (t < NGR) g_cnt[t] = 0.0f;
}

// ---------------- degree ----------------
__global__ void k_deg(const int* __restrict__ ei) {
    int e = blockIdx.x * blockDim.x + threadIdx.x;
    if (e < EE) {
        int dst = ei[EE + e];
        atomicAdd(&g_deg[dst], 1.0f);
        atomicAdd(&g_edeg[dst], 1);
    }
}

__global__ void k_dinv() {
    int i = blockIdx.x * blockDim.x + threadIdx.x;
    if (i < NN) g_dinv[i] = rsqrtf(g_deg[i]);
}

// ---------------- prefix scan over edge degrees -> CSR offsets ----------------
__global__ void k_scan() {
    __shared__ int sums[1024];
    int tid = threadIdx.x;
    const int CH = (NN + 1023) / 1024;  // 49
    int beg = tid * CH;
    int end = beg + CH; if (end > NN) end = NN;
    if (beg > NN) beg = NN;
    int s = 0;
    for (int i = beg; i < end; i++) s += g_edeg[i];
    sums[tid] = s;
    __syncthreads();
    for (int off = 1; off < 1024; off <<= 1) {
        int t = (tid >= off) ? sums[tid - off] : 0;
        __syncthreads();
        sums[tid] += t;
        __syncthreads();
    }
    int run = sums[tid] - s;  // exclusive prefix of this chunk
    for (int i = beg; i < end; i++) {
        g_off[i] = run;
        g_cursor[i] = run;
        run += g_edeg[i];
    }
    if (tid == 0) g_off[NN] = EE;
}

// ---------------- scatter edges into CSR by dst ----------------
__global__ void k_scatter(const int* __restrict__ ei) {
    int e = blockIdx.x * blockDim.x + threadIdx.x;
    if (e < EE) {
        int src = ei[e];
        int dst = ei[EE + e];
        int pos = atomicAdd(&g_cursor[dst], 1);
        g_csrc[pos] = src;
    }
}

// ---------------- tiled fp32 GEMM: C[M,64] = act(A[M,K]) @ W[K,64] ----------------
template <int K, bool RELU>
__device__ __forceinline__ void gemm_body(const float* __restrict__ A,
                                          const float* __restrict__ W,
                                          float* __restrict__ C, int M) {
    __shared__ float As[64][65];
    __shared__ float Ws[64][64];
    int tid = threadIdx.x;
    int tx = tid & 15, ty = tid >> 4;
    int row0 = blockIdx.x * 64;
    float acc[4][4] = {};

    for (int k0 = 0; k0 < K; k0 += 64) {
        // load A tile 64x64 (4 float4 per thread, coalesced)
        #pragma unroll
        for (int it = 0; it < 4; it++) {
            int l = tid + it * 256;
            int r = l >> 4, c4 = l & 15;
            int grow = row0 + r;
            float4 v = make_float4(0.f, 0.f, 0.f, 0.f);
            if (grow < M)
                v = *(const float4*)(A + (size_t)grow * K + k0 + c4 * 4);
            if (RELU) {
                v.x = fmaxf(v.x, 0.f); v.y = fmaxf(v.y, 0.f);
                v.z = fmaxf(v.z, 0.f); v.w = fmaxf(v.w, 0.f);
            }
            As[r][c4 * 4 + 0] = v.x; As[r][c4 * 4 + 1] = v.y;
            As[r][c4 * 4 + 2] = v.z; As[r][c4 * 4 + 3] = v.w;
        }
        // load W tile 64x64
        #pragma unroll
        for (int it = 0; it < 4; it++) {
            int l = tid + it * 256;
            int r = l >> 4, c4 = l & 15;
            *(float4*)&Ws[r][c4 * 4] =
                *(const float4*)(W + (size_t)(k0 + r) * 64 + c4 * 4);
        }
        __syncthreads();
        #pragma unroll
        for (int kk = 0; kk < 64; kk++) {
            float a0 = As[ty * 4 + 0][kk];
            float a1 = As[ty * 4 + 1][kk];
            float a2 = As[ty * 4 + 2][kk];
            float a3 = As[ty * 4 + 3][kk];
            float4 b = *(const float4*)&Ws[kk][tx * 4];
            acc[0][0] += a0 * b.x; acc[0][1] += a0 * b.y; acc[0][2] += a0 * b.z; acc[0][3] += a0 * b.w;
            acc[1][0] += a1 * b.x; acc[1][1] += a1 * b.y; acc[1][2] += a1 * b.z; acc[1][3] += a1 * b.w;
            acc[2][0] += a2 * b.x; acc[2][1] += a2 * b.y; acc[2][2] += a2 * b.z; acc[2][3] += a2 * b.w;
            acc[3][0] += a3 * b.x; acc[3][1] += a3 * b.y; acc[3][2] += a3 * b.z; acc[3][3] += a3 * b.w;
        }
        __syncthreads();
    }
    #pragma unroll
    for (int i = 0; i < 4; i++) {
        int grow = row0 + ty * 4 + i;
        if (grow < M) {
            float4 v = make_float4(acc[i][0], acc[i][1], acc[i][2], acc[i][3]);
            *(float4*)(C + (size_t)grow * 64 + tx * 4) = v;
        }
    }
}

__global__ void k_gemm1(const float* __restrict__ A, const float* __restrict__ W) {
    gemm_body<FIN, false>(A, W, g_h, NN);
}
__global__ void k_gemm2(const float* __restrict__ W) {
    gemm_body<HH, true>(g_a, W, g_h, NN);
}

// ---------------- aggregation: warp per dst node, register accumulation ----------------
// g_a[i] = bias + dinv[i]^2 * g_h[i] + sum_{e: dst=i} dinv[src]*dinv[i] * g_h[src]
__global__ void k_agg(const float* __restrict__ bias) {
    int gt = blockIdx.x * blockDim.x + threadIdx.x;
    int i = gt >> 5;
    int lane = threadIdx.x & 31;
    if (i >= NN) return;
    int beg = g_off[i], end = g_off[i + 1];
    float di = g_dinv[i];
    float2 hv = *(const float2*)(g_h + (size_t)i * HH + lane * 2);
    float s = di * di;
    float2 acc;
    acc.x = hv.x * s;
    acc.y = hv.y * s;
    for (int e = beg; e < end; e++) {
        int src = g_csrc[e];
        float norm = g_dinv[src] * di;
        float2 v = *(const float2*)(g_h + (size_t)src * HH + lane * 2);
        acc.x += v.x * norm;
        acc.y += v.y * norm;
    }
    const float2 b = *(const float2*)(bias + lane * 2);
    acc.x += b.x;
    acc.y += b.y;
    *(float2*)(g_a + (size_t)i * HH + lane * 2) = acc;
}

// ---------------- mean pool (relu fused) ----------------
__global__ void k_pool(const int* __restrict__ batch) {
    int t = blockIdx.x * blockDim.x + threadIdx.x;
    if (t >= NN * HH) return;
    int i = t >> 6, f = t & 63;
    int g = batch[i];
    float v = fmaxf(g_a[(size_t)i * HH + f], 0.f);
    atomicAdd(&g_pool[g * HH + f], v);
    if (f == 0) atomicAdd(&g_cnt[g], 1.0f);
}

// ---------------- MLP head ----------------
__global__ void k_mlp1(const float* __restrict__ w, const float* __restrict__ b) {
    int t = blockIdx.x * blockDim.x + threadIdx.x;
    if (t >= NGR * 128) return;
    int g = t >> 7, j = t & 127;
    float inv = 1.0f / fmaxf(g_cnt[g], 1.0f);
    float s = b[j];
    #pragma unroll 8
    for (int f = 0; f < HH; f++)
        s += (g_pool[g * HH + f] * inv) * w[f * 128 + j];
    g_z[t] = fmaxf(s, 0.f);
}

__global__ void k_mlp2(const float* __restrict__ w, const float* __restrict__ b,
                       float* __restrict__ out) {
    int t = threadIdx.x;
    if (t >= NGR * NCL) return;
    int g = t >> 2, c = t & 3;
    float s = b[c];
    #pragma unroll 16
    for (int j = 0; j < 128; j++)
        s += g_z[g * 128 + j] * w[j * NCL + c];
    out[t] = s;
}

// ---------------- launch ----------------
extern "C" void kernel_launch(void* const* d_in, const int* in_sizes, int n_in,
                              void* d_out, int out_size) {
    const float* x       = (const float*)d_in[0];
    const int* ei        = (const int*)d_in[1];
    const int* bat       = (const int*)d_in[2];
    const float* W1      = (const float*)d_in[3];
    const float* b1      = (const float*)d_in[4];
    const float* W2      = (const float*)d_in[5];
    const float* b2      = (const float*)d_in[6];
    const float* fc1w    = (const float*)d_in[7];
    const float* fc1b    = (const float*)d_in[8];
    const float* fc2w    = (const float*)d_in[9];
    const float* fc2b    = (const float*)d_in[10];
    float* out           = (float*)d_out;

    k_init<<<(NN + 255) / 256, 256>>>();
    k_deg<<<(EE + 255) / 256, 256>>>(ei);
    k_dinv<<<(NN + 255) / 256, 256>>>();
    k_scan<<<1, 1024>>>();
    k_scatter<<<(EE + 255) / 256, 256>>>(ei);

    // layer 1
    k_gemm1<<<(NN + 63) / 64, 256>>>(x, W1);
    k_agg<<<(NN * 32 + 255) / 256, 256>>>(b1);
    // layer 2 (relu fused into GEMM2's A-load)
    k_gemm2<<<(NN + 63) / 64, 256>>>(W2);
    k_agg<<<(NN * 32 + 255) / 256, 256>>>(b2);

    // pool + head
    k_pool<<<(NN * HH + 255) / 256, 256>>>(bat);
    k_mlp1<<<(NGR * 128 + 255) / 256, 256>>>(fc1w, fc1b);
    k_mlp2<<<1, 256>>>(fc2w, fc2b, out);
}

// round 4
// speedup vs baseline: 1.3650x; 1.3650x over previous
#include <cuda_runtime.h>
#include <cstdint>

// Problem constants (fixed by the reference)
#define NN 50000
#define EE 800000
#define FIN 256
#define HH 64
#define NGR 64
#define NCL 4

// ---------------- scratch (device globals; no allocs allowed) ----------------
__device__ int   g_edeg[NN];         // int in-edge count (no self loop)
__device__ float g_dinv[NN];
__device__ int   g_off[NN];          // CSR chunk start by dst (arbitrary chunk order)
__device__ int   g_cursor[NN];       // scatter cursors
__device__ int   g_csrc[EE];         // CSR src lists
__device__ int   g_counter;          // chunk allocator
__device__ float g_h[(size_t)NN * HH];   // X@W result (both layers)
__device__ float g_a[(size_t)NN * HH];   // aggregated output (both layers)
__device__ float g_pool[NGR * HH];
__device__ float g_cnt[NGR];
__device__ float g_z[NGR * 128];

// ---------------- init ----------------
__global__ void k_init() {
    int t = blockIdx.x * blockDim.x + threadIdx.x;
    if (t < NN) g_edeg[t] = 0;
    if (t < NGR * HH) g_pool[t] = 0.0f;
    if (t < NGR) g_cnt[t] = 0.0f;
    if (t == 0) g_counter = 0;
}

// ---------------- degree (in-edges only; self-loop added in dinv) ----------------
__global__ void k_deg(const int* __restrict__ ei) {
    int e = blockIdx.x * blockDim.x + threadIdx.x;
    if (e < EE) {
        int dst = ei[EE + e];
        atomicAdd(&g_edeg[dst], 1);
    }
}

__global__ void k_dinv() {
    int i = blockIdx.x * blockDim.x + threadIdx.x;
    if (i < NN) g_dinv[i] = rsqrtf((float)(g_edeg[i] + 1));
}

// ---------------- chunk allocation: warp-aggregated atomic (replaces scan) ----------------
__global__ void k_alloc() {
    int i = blockIdx.x * blockDim.x + threadIdx.x;
    int lane = threadIdx.x & 31;
    int v = (i < NN) ? g_edeg[i] : 0;
    // intra-warp inclusive scan
    int s = v;
    #pragma unroll
    for (int o = 1; o < 32; o <<= 1) {
        int t = __shfl_up_sync(0xFFFFFFFFu, s, o);
        if (lane >= o) s += t;
    }
    int total = __shfl_sync(0xFFFFFFFFu, s, 31);
    int base = 0;
    if (lane == 31) base = atomicAdd(&g_counter, total);
    base = __shfl_sync(0xFFFFFFFFu, base, 31);
    if (i < NN) {
        int beg = base + s - v;  // exclusive position
        g_off[i] = beg;
        g_cursor[i] = beg;
    }
}

// ---------------- scatter edges into CSR by dst ----------------
__global__ void k_scatter(const int* __restrict__ ei) {
    int e = blockIdx.x * blockDim.x + threadIdx.x;
    if (e < EE) {
        int src = ei[e];
        int dst = ei[EE + e];
        int pos = atomicAdd(&g_cursor[dst], 1);
        g_csrc[pos] = src;
    }
}

// ---------------- tiled fp32 GEMM: C[M,64] = act(A[M,K]) @ W[K,64] ----------------
template <int K, bool RELU>
__device__ __forceinline__ void gemm_body(const float* __restrict__ A,
                                          const float* __restrict__ W,
                                          float* __restrict__ C, int M) {
    __shared__ float As[64][65];
    __shared__ float Ws[64][64];
    int tid = threadIdx.x;
    int tx = tid & 15, ty = tid >> 4;
    int row0 = blockIdx.x * 64;
    float acc[4][4] = {};

    for (int k0 = 0; k0 < K; k0 += 64) {
        // load A tile 64x64 (4 float4 per thread, coalesced)
        #pragma unroll
        for (int it = 0; it < 4; it++) {
            int l = tid + it * 256;
            int r = l >> 4, c4 = l & 15;
            int grow = row0 + r;
            float4 v = make_float4(0.f, 0.f, 0.f, 0.f);
            if (grow < M)
                v = *(const float4*)(A + (size_t)grow * K + k0 + c4 * 4);
            if (RELU) {
                v.x = fmaxf(v.x, 0.f); v.y = fmaxf(v.y, 0.f);
                v.z = fmaxf(v.z, 0.f); v.w = fmaxf(v.w, 0.f);
            }
            As[r][c4 * 4 + 0] = v.x; As[r][c4 * 4 + 1] = v.y;
            As[r][c4 * 4 + 2] = v.z; As[r][c4 * 4 + 3] = v.w;
        }
        // load W tile 64x64
        #pragma unroll
        for (int it = 0; it < 4; it++) {
            int l = tid + it * 256;
            int r = l >> 4, c4 = l & 15;
            *(float4*)&Ws[r][c4 * 4] =
                *(const float4*)(W + (size_t)(k0 + r) * 64 + c4 * 4);
        }
        __syncthreads();
        #pragma unroll
        for (int kk = 0; kk < 64; kk++) {
            float a0 = As[ty * 4 + 0][kk];
            float a1 = As[ty * 4 + 1][kk];
            float a2 = As[ty * 4 + 2][kk];
            float a3 = As[ty * 4 + 3][kk];
            float4 b = *(const float4*)&Ws[kk][tx * 4];
            acc[0][0] += a0 * b.x; acc[0][1] += a0 * b.y; acc[0][2] += a0 * b.z; acc[0][3] += a0 * b.w;
            acc[1][0] += a1 * b.x; acc[1][1] += a1 * b.y; acc[1][2] += a1 * b.z; acc[1][3] += a1 * b.w;
            acc[2][0] += a2 * b.x; acc[2][1] += a2 * b.y; acc[2][2] += a2 * b.z; acc[2][3] += a2 * b.w;
            acc[3][0] += a3 * b.x; acc[3][1] += a3 * b.y; acc[3][2] += a3 * b.z; acc[3][3] += a3 * b.w;
        }
        __syncthreads();
    }
    #pragma unroll
    for (int i = 0; i < 4; i++) {
        int grow = row0 + ty * 4 + i;
        if (grow < M) {
            float4 v = make_float4(acc[i][0], acc[i][1], acc[i][2], acc[i][3]);
            *(float4*)(C + (size_t)grow * 64 + tx * 4) = v;
        }
    }
}

__global__ void k_gemm1(const float* __restrict__ A, const float* __restrict__ W) {
    gemm_body<FIN, false>(A, W, g_h, NN);
}
__global__ void k_gemm2(const float* __restrict__ W) {
    gemm_body<HH, true>(g_a, W, g_h, NN);
}

// ---------------- aggregation: warp per dst node, register accumulation ----------------
// g_a[i] = bias + dinv[i]^2 * g_h[i] + sum_{e: dst=i} dinv[src]*dinv[i] * g_h[src]
__global__ void k_agg(const float* __restrict__ bias) {
    int gt = blockIdx.x * blockDim.x + threadIdx.x;
    int i = gt >> 5;
    int lane = threadIdx.x & 31;
    if (i >= NN) return;
    int beg = g_off[i];
    int end = beg + g_edeg[i];
    float di = g_dinv[i];
    float2 hv = *(const float2*)(g_h + (size_t)i * HH + lane * 2);
    float s = di * di;
    float2 acc;
    acc.x = hv.x * s;
    acc.y = hv.y * s;
    for (int e = beg; e < end; e++) {
        int src = g_csrc[e];
        float norm = g_dinv[src] * di;
        float2 v = *(const float2*)(g_h + (size_t)src * HH + lane * 2);
        acc.x += v.x * norm;
        acc.y += v.y * norm;
    }
    const float2 b = *(const float2*)(bias + lane * 2);
    acc.x += b.x;
    acc.y += b.y;
    *(float2*)(g_a + (size_t)i * HH + lane * 2) = acc;
}

// ---------------- mean pool (relu fused); batch is SORTED ----------------
#define POOL_BLOCKS 256
__global__ void k_pool(const int* __restrict__ batch) {
    const int CH = (NN + POOL_BLOCKS - 1) / POOL_BLOCKS;  // 196
    int f = threadIdx.x;  // 0..63
    int beg = blockIdx.x * CH;
    int end = min(beg + CH, NN);
    if (beg >= end) return;
    float acc = 0.f;
    float cnt = 0.f;
    int curg = batch[beg];
    for (int i = beg; i < end; i++) {
        int g = batch[i];
        if (g != curg) {
            atomicAdd(&g_pool[curg * HH + f], acc);
            if (f == 0) atomicAdd(&g_cnt[curg], cnt);
            acc = 0.f; cnt = 0.f; curg = g;
        }
        acc += fmaxf(g_a[(size_t)i * HH + f], 0.f);
        cnt += 1.f;
    }
    atomicAdd(&g_pool[curg * HH + f], acc);
    if (f == 0) atomicAdd(&g_cnt[curg], cnt);
}

// ---------------- MLP head ----------------
__global__ void k_mlp1(const float* __restrict__ w, const float* __restrict__ b) {
    int t = blockIdx.x * blockDim.x + threadIdx.x;
    if (t >= NGR * 128) return;
    int g = t >> 7, j = t & 127;
    float inv = 1.0f / fmaxf(g_cnt[g], 1.0f);
    float s = b[j];
    #pragma unroll 8
    for (int f = 0; f < HH; f++)
        s += (g_pool[g * HH + f] * inv) * w[f * 128 + j];
    g_z[t] = fmaxf(s, 0.f);
}

__global__ void k_mlp2(const float* __restrict__ w, const float* __restrict__ b,
                       float* __restrict__ out) {
    int t = threadIdx.x;
    if (t >= NGR * NCL) return;
    int g = t >> 2, c = t & 3;
    float s = b[c];
    #pragma unroll 16
    for (int j = 0; j < 128; j++)
        s += g_z[g * 128 + j] * w[j * NCL + c];
    out[t] = s;
}

// ---------------- launch ----------------
extern "C" void kernel_launch(void* const* d_in, const int* in_sizes, int n_in,
                              void* d_out, int out_size) {
    const float* x       = (const float*)d_in[0];
    const int* ei        = (const int*)d_in[1];
    const int* bat       = (const int*)d_in[2];
    const float* W1      = (const float*)d_in[3];
    const float* b1      = (const float*)d_in[4];
    const float* W2      = (const float*)d_in[5];
    const float* b2      = (const float*)d_in[6];
    const float* fc1w    = (const float*)d_in[7];
    const float* fc1b    = (const float*)d_in[8];
    const float* fc2w    = (const float*)d_in[9];
    const float* fc2b    = (const float*)d_in[10];
    float* out           = (float*)d_out;

    k_init<<<(NN + 255) / 256, 256>>>();
    k_deg<<<(EE + 255) / 256, 256>>>(ei);
    k_dinv<<<(NN + 255) / 256, 256>>>();
    k_alloc<<<(NN + 255) / 256, 256>>>();
    k_scatter<<<(EE + 255) / 256, 256>>>(ei);

    // layer 1
    k_gemm1<<<(NN + 63) / 64, 256>>>(x, W1);
    k_agg<<<(NN * 32 + 255) / 256, 256>>>(b1);
    // layer 2 (relu fused into GEMM2's A-load)
    k_gemm2<<<(NN + 63) / 64, 256>>>(W2);
    k_agg<<<(NN * 32 + 255) / 256, 256>>>(b2);

    // pool + head
    k_pool<<<POOL_BLOCKS, HH>>>(bat);
    k_mlp1<<<(NGR * 128 + 255) / 256, 256>>>(fc1w, fc1b);
    k_mlp2<<<1, 256>>>(fc2w, fc2b, out);
}

// round 6
// speedup vs baseline: 1.4824x; 1.0860x over previous
#include <cuda_runtime.h>
#include <cstdint>

// Problem constants (fixed by the reference)
#define NN 50000
#define EE 800000
#define FIN 256
#define HH 64
#define NGR 64
#define NCL 4

// ---------------- scratch (device globals; no allocs allowed) ----------------
__device__ int   g_edeg[NN];         // int in-edge count (no self loop)
__device__ float g_dinv[NN];
__device__ int   g_off[NN];          // CSR chunk start by dst (arbitrary chunk order)
__device__ int   g_cursor[NN];       // scatter cursors
__device__ int   g_csrc[EE];         // CSR src lists
__device__ int   g_counter;          // chunk allocator
__device__ float g_h[(size_t)NN * HH];   // X@W result (both layers)
__device__ float g_a[(size_t)NN * HH];   // aggregated output (both layers)
__device__ float g_pool[NGR * HH];
__device__ float g_cnt[NGR];
__device__ float g_z[NGR * 128];

// ---------------- init ----------------
__global__ void k_init() {
    int t = blockIdx.x * blockDim.x + threadIdx.x;
    if (t < NN) g_edeg[t] = 0;
    if (t < NGR * HH) g_pool[t] = 0.0f;
    if (t < NGR) g_cnt[t] = 0.0f;
    if (t == 0) g_counter = 0;
}

// ---------------- degree (in-edges only; self-loop added in dinv) ----------------
__global__ void k_deg(const int* __restrict__ ei) {
    int e = blockIdx.x * blockDim.x + threadIdx.x;
    if (e < EE) {
        int dst = ei[EE + e];
        atomicAdd(&g_edeg[dst], 1);
    }
}

// ---------------- chunk allocation + dinv (warp-aggregated atomic) ----------------
__global__ void k_alloc() {
    int i = blockIdx.x * blockDim.x + threadIdx.x;
    int lane = threadIdx.x & 31;
    int v = (i < NN) ? g_edeg[i] : 0;
    // intra-warp inclusive scan
    int s = v;
    #pragma unroll
    for (int o = 1; o < 32; o <<= 1) {
        int t = __shfl_up_sync(0xFFFFFFFFu, s, o);
        if (lane >= o) s += t;
    }
    int total = __shfl_sync(0xFFFFFFFFu, s, 31);
    int base = 0;
    if (lane == 31) base = atomicAdd(&g_counter, total);
    base = __shfl_sync(0xFFFFFFFFu, base, 31);
    if (i < NN) {
        int beg = base + s - v;  // exclusive position
        g_off[i] = beg;
        g_cursor[i] = beg;
        g_dinv[i] = rsqrtf((float)(v + 1));
    }
}

// ---------------- scatter edges into CSR by dst ----------------
__global__ void k_scatter(const int* __restrict__ ei) {
    int e = blockIdx.x * blockDim.x + threadIdx.x;
    if (e < EE) {
        int src = ei[e];
        int dst = ei[EE + e];
        int pos = atomicAdd(&g_cursor[dst], 1);
        g_csrc[pos] = src;
    }
}

// ---------------- tiled fp32 GEMM: C[M,64] = act(A[M,K]) @ W[K,64] ----------------
template <int K, bool RELU>
__device__ __forceinline__ void gemm_body(const float* __restrict__ A,
                                          const float* __restrict__ W,
                                          float* __restrict__ C, int M) {
    __shared__ float As[64][65];
    __shared__ float Ws[64][64];
    int tid = threadIdx.x;
    int tx = tid & 15, ty = tid >> 4;
    int row0 = blockIdx.x * 64;
    float acc[4][4] = {};

    for (int k0 = 0; k0 < K; k0 += 64) {
        // load A tile 64x64 (4 float4 per thread, coalesced)
        #pragma unroll
        for (int it = 0; it < 4; it++) {
            int l = tid + it * 256;
            int r = l >> 4, c4 = l & 15;
            int grow = row0 + r;
            float4 v = make_float4(0.f, 0.f, 0.f, 0.f);
            if (grow < M)
                v = *(const float4*)(A + (size_t)grow * K + k0 + c4 * 4);
            if (RELU) {
                v.x = fmaxf(v.x, 0.f); v.y = fmaxf(v.y, 0.f);
                v.z = fmaxf(v.z, 0.f); v.w = fmaxf(v.w, 0.f);
            }
            As[r][c4 * 4 + 0] = v.x; As[r][c4 * 4 + 1] = v.y;
            As[r][c4 * 4 + 2] = v.z; As[r][c4 * 4 + 3] = v.w;
        }
        // load W tile 64x64
        #pragma unroll
        for (int it = 0; it < 4; it++) {
            int l = tid + it * 256;
            int r = l >> 4, c4 = l & 15;
            *(float4*)&Ws[r][c4 * 4] =
                *(const float4*)(W + (size_t)(k0 + r) * 64 + c4 * 4);
        }
        __syncthreads();
        #pragma unroll
        for (int kk = 0; kk < 64; kk++) {
            float a0 = As[ty * 4 + 0][kk];
            float a1 = As[ty * 4 + 1][kk];
            float a2 = As[ty * 4 + 2][kk];
            float a3 = As[ty * 4 + 3][kk];
            float4 b = *(const float4*)&Ws[kk][tx * 4];
            acc[0][0] += a0 * b.x; acc[0][1] += a0 * b.y; acc[0][2] += a0 * b.z; acc[0][3] += a0 * b.w;
            acc[1][0] += a1 * b.x; acc[1][1] += a1 * b.y; acc[1][2] += a1 * b.z; acc[1][3] += a1 * b.w;
            acc[2][0] += a2 * b.x; acc[2][1] += a2 * b.y; acc[2][2] += a2 * b.z; acc[2][3] += a2 * b.w;
            acc[3][0] += a3 * b.x; acc[3][1] += a3 * b.y; acc[3][2] += a3 * b.z; acc[3][3] += a3 * b.w;
        }
        __syncthreads();
    }
    #pragma unroll
    for (int i = 0; i < 4; i++) {
        int grow = row0 + ty * 4 + i;
        if (grow < M) {
            float4 v = make_float4(acc[i][0], acc[i][1], acc[i][2], acc[i][3]);
            *(float4*)(C + (size_t)grow * 64 + tx * 4) = v;
        }
    }
}

__global__ void k_gemm1(const float* __restrict__ A, const float* __restrict__ W) {
    gemm_body<FIN, false>(A, W, g_h, NN);
}
__global__ void k_gemm2(const float* __restrict__ W) {
    gemm_body<HH, true>(g_a, W, g_h, NN);
}

// ---------------- aggregation: warp per dst node, register accumulation ----------------
// g_a[i] = bias + dinv[i]^2 * g_h[i] + sum_{e: dst=i} dinv[src]*dinv[i] * g_h[src]
__global__ void k_agg(const float* __restrict__ bias) {
    int gt = blockIdx.x * blockDim.x + threadIdx.x;
    int i = gt >> 5;
    int lane = threadIdx.x & 31;
    if (i >= NN) return;
    int beg = g_off[i];
    int end = beg + g_edeg[i];
    float di = g_dinv[i];
    float2 hv = *(const float2*)(g_h + (size_t)i * HH + lane * 2);
    float s = di * di;
    float2 acc;
    acc.x = hv.x * s;
    acc.y = hv.y * s;
    for (int e = beg; e < end; e++) {
        int src = g_csrc[e];
        float norm = g_dinv[src] * di;
        float2 v = *(const float2*)(g_h + (size_t)src * HH + lane * 2);
        acc.x += v.x * norm;
        acc.y += v.y * norm;
    }
    const float2 b = *(const float2*)(bias + lane * 2);
    acc.x += b.x;
    acc.y += b.y;
    *(float2*)(g_a + (size_t)i * HH + lane * 2) = acc;
}

// ---------------- mean pool (relu fused); batch is SORTED ----------------
#define POOL_BLOCKS 256
__global__ void k_pool(const int* __restrict__ batch) {
    const int CH = (NN + POOL_BLOCKS - 1) / POOL_BLOCKS;  // 196
    int f = threadIdx.x;  // 0..63
    int beg = blockIdx.x * CH;
    int end = min(beg + CH, NN);
    if (beg >= end) return;
    float acc = 0.f;
    float cnt = 0.f;
    int curg = batch[beg];
    for (int i = beg; i < end; i++) {
        int g = batch[i];
        if (g != curg) {
            atomicAdd(&g_pool[curg * HH + f], acc);
            if (f == 0) atomicAdd(&g_cnt[curg], cnt);
            acc = 0.f; cnt = 0.f; curg = g;
        }
        acc += fmaxf(g_a[(size_t)i * HH + f], 0.f);
        cnt += 1.f;
    }
    atomicAdd(&g_pool[curg * HH + f], acc);
    if (f == 0) atomicAdd(&g_cnt[curg], cnt);
}

// ---------------- MLP head ----------------
__global__ void k_mlp1(const float* __restrict__ w, const float* __restrict__ b) {
    int t = blockIdx.x * blockDim.x + threadIdx.x;
    if (t >= NGR * 128) return;
    int g = t >> 7, j = t & 127;
    float inv = 1.0f / fmaxf(g_cnt[g], 1.0f);
    float s = b[j];
    #pragma unroll 8
    for (int f = 0; f < HH; f++)
        s += (g_pool[g * HH + f] * inv) * w[f * 128 + j];
    g_z[t] = fmaxf(s, 0.f);
}

__global__ void k_mlp2(const float* __restrict__ w, const float* __restrict__ b,
                       float* __restrict__ out) {
    int t = threadIdx.x;
    if (t >= NGR * NCL) return;
    int g = t >> 2, c = t & 3;
    float s = b[c];
    #pragma unroll 16
    for (int j = 0; j < 128; j++)
        s += g_z[g * 128 + j] * w[j * NCL + c];
    out[t] = s;
}

// ---------------- launch ----------------
extern "C" void kernel_launch(void* const* d_in, const int* in_sizes, int n_in,
                              void* d_out, int out_size) {
    const float* x       = (const float*)d_in[0];
    const int* ei        = (const int*)d_in[1];
    const int* bat       = (const int*)d_in[2];
    const float* W1      = (const float*)d_in[3];
    const float* b1      = (const float*)d_in[4];
    const float* W2      = (const float*)d_in[5];
    const float* b2      = (const float*)d_in[6];
    const float* fc1w    = (const float*)d_in[7];
    const float* fc1b    = (const float*)d_in[8];
    const float* fc2w    = (const float*)d_in[9];
    const float* fc2b    = (const float*)d_in[10];
    float* out           = (float*)d_out;

    // one-time creation of side stream + events (host objects, not device memory;
    // created during the non-captured correctness call, reused identically every call)
    static cudaStream_t s_pre = nullptr;
    static cudaEvent_t ev_root = nullptr, ev_pre = nullptr;
    if (!s_pre) {
        cudaStreamCreateWithFlags(&s_pre, cudaStreamNonBlocking);
        cudaEventCreateWithFlags(&ev_root, cudaEventDisableTiming);
        cudaEventCreateWithFlags(&ev_pre, cudaEventDisableTiming);
    }

    // fork: preprocessing chain on side stream, overlapped with gemm1
    cudaEventRecord(ev_root, 0);
    cudaStreamWaitEvent(s_pre, ev_root, 0);

    k_init<<<(NN + 255) / 256, 256, 0, s_pre>>>();
    k_deg<<<(EE + 255) / 256, 256, 0, s_pre>>>(ei);
    k_alloc<<<(NN + 255) / 256, 256, 0, s_pre>>>();
    k_scatter<<<(EE + 255) / 256, 256, 0, s_pre>>>(ei);
    cudaEventRecord(ev_pre, s_pre);

    // main stream: gemm1 (independent of CSR build)
    k_gemm1<<<(NN + 63) / 64, 256>>>(x, W1);

    // join before aggregation
    cudaStreamWaitEvent(0, ev_pre, 0);

    // layer 1 aggregation
    k_agg<<<(NN * 32 + 255) / 256, 256>>>(b1);
    // layer 2 (relu fused into GEMM2's A-load)
    k_gemm2<<<(NN + 63) / 64, 256>>>(W2);
    k_agg<<<(NN * 32 + 255) / 256, 256>>>(b2);

    // pool + head
    k_pool<<<POOL_BLOCKS, HH>>>(bat);
    k_mlp1<<<(NGR * 128 + 255) / 256, 256>>>(fc1w, fc1b);
    k_mlp2<<<1, 256>>>(fc2w, fc2b, out);
}

// round 12
// speedup vs baseline: 1.5281x; 1.0308x over previous
#include <cuda_runtime.h>
#include <cstdint>

// Problem constants (fixed by the reference)
#define NN 50000
#define EE 800000
#define FIN 256
#define HH 64
#define NGR 64
#define NCL 4

// ---------------- scratch (device globals; no allocs allowed) ----------------
__device__ int   g_edeg[NN];
__device__ float g_dinv[NN];
__device__ int   g_off[NN];
__device__ int   g_cursor[NN];
__device__ int   g_csrc[EE];
__device__ int   g_counter;
__device__ __align__(128) float g_h[(size_t)NN * HH];
__device__ __align__(128) float g_a[(size_t)NN * HH];
__device__ float g_pool[NGR * HH];
__device__ float g_cnt[NGR];

// ---------------- init ----------------
__global__ void k_init() {
    int t = blockIdx.x * blockDim.x + threadIdx.x;
    if (t < NN) g_edeg[t] = 0;
    if (t < NGR * HH) g_pool[t] = 0.0f;
    if (t < NGR) g_cnt[t] = 0.0f;
    if (t == 0) g_counter = 0;
}

// ---------------- degree ----------------
__global__ void k_deg(const int* __restrict__ ei) {
    int e = blockIdx.x * blockDim.x + threadIdx.x;
    if (e < EE) atomicAdd(&g_edeg[ei[EE + e]], 1);
}

// ---------------- chunk allocation + dinv (warp-aggregated atomic) ----------------
__global__ void k_alloc() {
    int i = blockIdx.x * blockDim.x + threadIdx.x;
    int lane = threadIdx.x & 31;
    int v = (i < NN) ? g_edeg[i] : 0;
    int s = v;
    #pragma unroll
    for (int o = 1; o < 32; o <<= 1) {
        int t = __shfl_up_sync(0xFFFFFFFFu, s, o);
        if (lane >= o) s += t;
    }
    int total = __shfl_sync(0xFFFFFFFFu, s, 31);
    int base = 0;
    if (lane == 31) base = atomicAdd(&g_counter, total);
    base = __shfl_sync(0xFFFFFFFFu, base, 31);
    if (i < NN) {
        int beg = base + s - v;
        g_off[i] = beg;
        g_cursor[i] = beg;
        g_dinv[i] = rsqrtf((float)(v + 1));
    }
}

// ---------------- scatter ----------------
__global__ void k_scatter(const int* __restrict__ ei) {
    int e = blockIdx.x * blockDim.x + threadIdx.x;
    if (e < EE) {
        int src = ei[e];
        int dst = ei[EE + e];
        int pos = atomicAdd(&g_cursor[dst], 1);
        g_csrc[pos] = src;
    }
}

// ---------------- packed f32x2 helpers ----------------
__device__ __forceinline__ unsigned long long splat2(float a) {
    unsigned long long r;
    asm("mov.b64 %0, {%1, %1};" : "=l"(r) : "f"(a));
    return r;
}
__device__ __forceinline__ void fma2(unsigned long long& acc, unsigned long long a,
                                     unsigned long long b) {
    asm("fma.rn.f32x2 %0, %1, %2, %0;" : "+l"(acc) : "l"(a), "l"(b));
}
__device__ __forceinline__ float2 unpack2(unsigned long long v) {
    float2 r;
    asm("mov.b64 {%0, %1}, %2;" : "=f"(r.x), "=f"(r.y) : "l"(v));
    return r;
}

// ---------------- tiled fp32 GEMM w/ packed FFMA2: C[M,64] = act(A[M,K]) @ W[K,64] ------
template <int K, bool RELU>
__device__ __forceinline__ void gemm_body(const float* __restrict__ A,
                                          const float* __restrict__ W,
                                          float* __restrict__ C, int M) {
    __shared__ float As[64][65];
    __shared__ __align__(16) float Ws[64][64];
    int tid = threadIdx.x;
    int tx = tid & 15, ty = tid >> 4;
    int row0 = blockIdx.x * 64;
    // acc[i] pairs: cols (tx*4+0, tx*4+1) in acc01[i], (tx*4+2, tx*4+3) in acc23[i]
    unsigned long long acc01[4] = {0ull, 0ull, 0ull, 0ull};
    unsigned long long acc23[4] = {0ull, 0ull, 0ull, 0ull};

    for (int k0 = 0; k0 < K; k0 += 64) {
        // load A tile 64x64 (coalesced float4)
        #pragma unroll
        for (int it = 0; it < 4; it++) {
            int l = tid + it * 256;
            int r = l >> 4, c4 = l & 15;
            int grow = row0 + r;
            float4 v = make_float4(0.f, 0.f, 0.f, 0.f);
            if (grow < M)
                v = *(const float4*)(A + (size_t)grow * K + k0 + c4 * 4);
            if (RELU) {
                v.x = fmaxf(v.x, 0.f); v.y = fmaxf(v.y, 0.f);
                v.z = fmaxf(v.z, 0.f); v.w = fmaxf(v.w, 0.f);
            }
            As[r][c4 * 4 + 0] = v.x; As[r][c4 * 4 + 1] = v.y;
            As[r][c4 * 4 + 2] = v.z; As[r][c4 * 4 + 3] = v.w;
        }
        // load W tile 64x64
        #pragma unroll
        for (int it = 0; it < 4; it++) {
            int l = tid + it * 256;
            int r = l >> 4, c4 = l & 15;
            *(float4*)&Ws[r][c4 * 4] =
                *(const float4*)(W + (size_t)(k0 + r) * 64 + c4 * 4);
        }
        __syncthreads();
        #pragma unroll
        for (int kk = 0; kk < 64; kk++) {
            // b pair-of-pairs directly from 16B-aligned shared load
            const double2 bb = *(const double2*)&Ws[kk][tx * 4];
            unsigned long long b01 = __double_as_longlong(bb.x);
            unsigned long long b23 = __double_as_longlong(bb.y);
            unsigned long long s0 = splat2(As[ty * 4 + 0][kk]);
            unsigned long long s1 = splat2(As[ty * 4 + 1][kk]);
            unsigned long long s2 = splat2(As[ty * 4 + 2][kk]);
            unsigned long long s3 = splat2(As[ty * 4 + 3][kk]);
            fma2(acc01[0], s0, b01); fma2(acc23[0], s0, b23);
            fma2(acc01[1], s1, b01); fma2(acc23[1], s1, b23);
            fma2(acc01[2], s2, b01); fma2(acc23[2], s2, b23);
            fma2(acc01[3], s3, b01); fma2(acc23[3], s3, b23);
        }
        __syncthreads();
    }
    #pragma unroll
    for (int i = 0; i < 4; i++) {
        int grow = row0 + ty * 4 + i;
        if (grow < M) {
            float2 p01 = unpack2(acc01[i]);
            float2 p23 = unpack2(acc23[i]);
            float4 v = make_float4(p01.x, p01.y, p23.x, p23.y);
            *(float4*)(C + (size_t)grow * 64 + tx * 4) = v;
        }
    }
}

__global__ void __launch_bounds__(256) k_gemm1(const float* __restrict__ A,
                                               const float* __restrict__ W) {
    gemm_body<FIN, false>(A, W, g_h, NN);
}
__global__ void __launch_bounds__(256) k_gemm2(const float* __restrict__ W) {
    gemm_body<HH, true>(g_a, W, g_h, NN);
}

// ---------------- aggregation: warp per dst node ----------------
__global__ void k_agg(const float* __restrict__ bias) {
    int gt = blockIdx.x * blockDim.x + threadIdx.x;
    int i = gt >> 5;
    int lane = threadIdx.x & 31;
    if (i >= NN) return;
    int beg = g_off[i];
    int end = beg + g_edeg[i];
    float di = g_dinv[i];
    float2 hv = *(const float2*)(g_h + (size_t)i * HH + lane * 2);
    float s = di * di;
    float2 acc;
    acc.x = hv.x * s;
    acc.y = hv.y * s;
    for (int e = beg; e < end; e++) {
        int src = g_csrc[e];
        float norm = g_dinv[src] * di;
        float2 v = *(const float2*)(g_h + (size_t)src * HH + lane * 2);
        acc.x += v.x * norm;
        acc.y += v.y * norm;
    }
    const float2 b = *(const float2*)(bias + lane * 2);
    acc.x += b.x;
    acc.y += b.y;
    *(float2*)(g_a + (size_t)i * HH + lane * 2) = acc;
}

// ---------------- mean pool (relu fused); batch is SORTED ----------------
#define POOL_BLOCKS 256
__global__ void k_pool(const int* __restrict__ batch) {
    const int CH = (NN + POOL_BLOCKS - 1) / POOL_BLOCKS;
    int f = threadIdx.x;
    int beg = blockIdx.x * CH;
    int end = min(beg + CH, NN);
    if (beg >= end) return;
    float acc = 0.f, cnt = 0.f;
    int curg = batch[beg];
    for (int i = beg; i < end; i++) {
        int g = batch[i];
        if (g != curg) {
            atomicAdd(&g_pool[curg * HH + f], acc);
            if (f == 0) atomicAdd(&g_cnt[curg], cnt);
            acc = 0.f; cnt = 0.f; curg = g;
        }
        acc += fmaxf(g_a[(size_t)i * HH + f], 0.f);
        cnt += 1.f;
    }
    atomicAdd(&g_pool[curg * HH + f], acc);
    if (f == 0) atomicAdd(&g_cnt[curg], cnt);
}

// ---------------- fused MLP head: one block per graph ----------------
__global__ void k_head(const float* __restrict__ fc1w, const float* __restrict__ fc1b,
                       const float* __restrict__ fc2w, const float* __restrict__ fc2b,
                       float* __restrict__ out) {
    __shared__ float z[128];
    int g = blockIdx.x;
    int j = threadIdx.x;   // 0..127
    float inv = 1.0f / fmaxf(g_cnt[g], 1.0f);
    float s = fc1b[j];
    #pragma unroll 8
    for (int f = 0; f < HH; f++)
        s += (g_pool[g * HH + f] * inv) * fc1w[f * 128 + j];
    z[j] = fmaxf(s, 0.f);
    __syncthreads();
    if (j < NCL) {
        float o = fc2b[j];
        #pragma unroll 16
        for (int q = 0; q < 128; q++)
            o += z[q] * fc2w[q * NCL + j];
        out[g * NCL + j] = o;
    }
}

// ---------------- launch ----------------
extern "C" void kernel_launch(void* const* d_in, const int* in_sizes, int n_in,
                              void* d_out, int out_size) {
    const float* x    = (const float*)d_in[0];
    const int* ei     = (const int*)d_in[1];
    const int* bat    = (const int*)d_in[2];
    const float* W1   = (const float*)d_in[3];
    const float* b1   = (const float*)d_in[4];
    const float* W2   = (const float*)d_in[5];
    const float* b2   = (const float*)d_in[6];
    const float* fc1w = (const float*)d_in[7];
    const float* fc1b = (const float*)d_in[8];
    const float* fc2w = (const float*)d_in[9];
    const float* fc2b = (const float*)d_in[10];
    float* out        = (float*)d_out;

    static cudaStream_t s_pre = nullptr;
    static cudaEvent_t ev_root = nullptr, ev_pre = nullptr;
    if (!s_pre) {
        cudaStreamCreateWithFlags(&s_pre, cudaStreamNonBlocking);
        cudaEventCreateWithFlags(&ev_root, cudaEventDisableTiming);
        cudaEventCreateWithFlags(&ev_pre, cudaEventDisableTiming);
    }

    // fork: CSR build on side stream, overlapped with gemm1
    cudaEventRecord(ev_root, 0);
    cudaStreamWaitEvent(s_pre, ev_root, 0);
    k_init<<<(NN + 255) / 256, 256, 0, s_pre>>>();
    k_deg<<<(EE + 255) / 256, 256, 0, s_pre>>>(ei);
    k_alloc<<<(NN + 255) / 256, 256, 0, s_pre>>>();
    k_scatter<<<(EE + 255) / 256, 256, 0, s_pre>>>(ei);
    cudaEventRecord(ev_pre, s_pre);

    // main stream: gemm1 (independent of CSR build)
    k_gemm1<<<(NN + 63) / 64, 256>>>(x, W1);

    cudaStreamWaitEvent(0, ev_pre, 0);

    k_agg<<<(NN * 32 + 255) / 256, 256>>>(b1);
    k_gemm2<<<(NN + 63) / 64, 256>>>(W2);
    k_agg<<<(NN * 32 + 255) / 256, 256>>>(b2);

    k_pool<<<POOL_BLOCKS, HH>>>(bat);
    k_head<<<NGR, 128>>>(fc1w, fc1b, fc2w, fc2b, out);
}